// round 1
// baseline (speedup 1.0000x reference)
#include <cuda_runtime.h>

#define Bn 64
#define Ln 200
#define Dn 256
#define Kn 8
#define BLn (Bn*Ln)
#define EPSF 1e-5f
#define SCALEF 0.0625f

// ---------------- device scratch (no allocations allowed) ----------------
__device__ float  g_Wt[Dn*Dn];       // W_w transposed: Wt[j][d] = W_w[d][j]
__device__ float4 g_stats[2*BLn];    // (mu1, var1, mu2, rstd2) per (branch,row)
__device__ float  g_I2[Kn*Dn];       // ln2(intentions)
__device__ float  g_q[2*Bn*Dn];      // ln3(q_row)
__device__ float  g_score[2*BLn*Kn]; // softmax over K
__device__ float  g_qkh[2*BLn];      // q . key_hat   (raw)
__device__ float  g_glog[2*BLn];     // q . relu(KH W^T + b)  (raw)
__device__ float  g_w[2*BLn];        // softmax over L

// ---------------- helpers ----------------
__device__ __forceinline__ float warpSum(float v){
#pragma unroll
  for(int o=16;o>0;o>>=1) v += __shfl_xor_sync(0xffffffffu, v, o);
  return v;
}
__device__ __forceinline__ float warpMax(float v){
#pragma unroll
  for(int o=16;o>0;o>>=1) v = fmaxf(v, __shfl_xor_sync(0xffffffffu, v, o));
  return v;
}
__device__ __forceinline__ unsigned long long fma2u(unsigned long long a,
                                                   unsigned long long b,
                                                   unsigned long long c){
  unsigned long long d;
  asm("fma.rn.f32x2 %0, %1, %2, %3;" : "=l"(d) : "l"(a), "l"(b), "l"(c));
  return d;
}
__device__ __forceinline__ float2 up2(unsigned long long v){
  float2 r;
  asm("mov.b64 {%0,%1}, %2;" : "=f"(r.x), "=f"(r.y) : "l"(v));
  return r;
}

// ---------------- 1. transpose W_w -> g_Wt ----------------
__global__ void k_tr(const float* __restrict__ W){
  __shared__ float t[32][33];
  int x0 = blockIdx.x*32, y0 = blockIdx.y*32;
  t[threadIdx.y][threadIdx.x] = W[(y0+threadIdx.y)*Dn + x0+threadIdx.x];
  __syncthreads();
  g_Wt[(x0+threadIdx.y)*Dn + y0+threadIdx.x] = t[threadIdx.x][threadIdx.y];
}

// ---------------- 2. per-row stats of x and x+pos ----------------
__global__ void k_stats(const float* __restrict__ xl, const float* __restrict__ xg,
                        const float* __restrict__ pos){
  int i = blockIdx.x;                 // 0 .. 2*BL-1
  int which = i / BLn; int row = i - which*BLn;
  const float* x = which ? xg : xl;
  int l = row % Ln;
  int d = threadIdx.x;
  float s  = x[row*Dn + d];
  float sp = s + pos[l*Dn + d];
  float a0 = warpSum(s), a1 = warpSum(s*s), a2 = warpSum(sp), a3 = warpSum(sp*sp);
  __shared__ float4 sm[8];
  int w = d>>5, ln = d&31;
  if(ln==0) sm[w] = make_float4(a0,a1,a2,a3);
  __syncthreads();
  if(w==0){
    float4 v = (ln<8)? sm[ln] : make_float4(0.f,0.f,0.f,0.f);
    v.x=warpSum(v.x); v.y=warpSum(v.y); v.z=warpSum(v.z); v.w=warpSum(v.w);
    if(ln==0){
      float mu1=v.x/Dn, var1=v.y/Dn-mu1*mu1;
      float mu2=v.z/Dn, var2=v.w/Dn-mu2*mu2;
      g_stats[i] = make_float4(mu1, var1, mu2, rsqrtf(var2+EPSF));
    }
  }
}

// ---------------- 3. ln2(intentions) ----------------
__global__ void k_lnint(const float* __restrict__ intent,
                        const float* __restrict__ g2, const float* __restrict__ b2){
  int k = blockIdx.x, d = threadIdx.x;
  float v = intent[k*Dn + d];
  __shared__ float s1[8], s2[8], res[2];
  float a = warpSum(v), b = warpSum(v*v);
  int w = d>>5, ln = d&31;
  if(ln==0){ s1[w]=a; s2[w]=b; }
  __syncthreads();
  if(d==0){
    float t1=0.f, t2=0.f;
    for(int u=0;u<8;u++){ t1+=s1[u]; t2+=s2[u]; }
    float mu=t1/Dn, var=t2/Dn-mu*mu;
    res[0]=mu; res[1]=rsqrtf(var+EPSF);
  }
  __syncthreads();
  g_I2[k*Dn+d] = (v-res[0])*res[1]*g2[d] + b2[d];
}

// ---------------- 4. q = ln3(x[b,last] + pos[last] + rou) ----------------
__global__ void k_q(const float* __restrict__ xl, const float* __restrict__ xg,
                    const float* __restrict__ pos, const float* __restrict__ rou,
                    const float* __restrict__ g3, const float* __restrict__ b3,
                    const int* __restrict__ seq){
  int i = blockIdx.x; int which = i/Bn; int b = i - which*Bn; int d = threadIdx.x;
  const float* x = which ? xg : xl;
  int idx = seq[b] - 1;
  float v = x[(b*Ln+idx)*Dn + d] + pos[idx*Dn + d] + rou[d];
  __shared__ float s1[8], s2[8], res[2];
  float a = warpSum(v), bb = warpSum(v*v);
  int w = d>>5, ln = d&31;
  if(ln==0){ s1[w]=a; s2[w]=bb; }
  __syncthreads();
  if(d==0){
    float t1=0.f, t2=0.f;
    for(int u=0;u<8;u++){ t1+=s1[u]; t2+=s2[u]; }
    float mu=t1/Dn, var=t2/Dn-mu*mu;
    res[0]=mu; res[1]=rsqrtf(var+EPSF);
  }
  __syncthreads();
  g_q[i*Dn+d] = (v-res[0])*res[1]*g3[d] + b3[d];
}

// ---------------- 5. score softmax over K  +  q.key_hat ----------------
__global__ void k_score(const float* __restrict__ xl, const float* __restrict__ xg,
                        const float* __restrict__ pos,
                        const float* __restrict__ g1, const float* __restrict__ b1,
                        const float* __restrict__ g4, const float* __restrict__ b4){
  int i = blockIdx.x; int which = i/BLn; int row = i - which*BLn;
  const float* x = which ? xg : xl;
  int b = row/Ln, l = row - b*Ln, d = threadIdx.x;
  float4 st = g_stats[i];
  float xv = x[row*Dn + d];
  float rs1 = rsqrtf(st.y + EPSF);
  float ln1v = (xv - st.x)*rs1*g1[d] + b1[d];
  float khv  = (xv + pos[l*Dn+d] - st.z)*st.w*g4[d] + b4[d];
  float qv = g_q[(which*Bn+b)*Dn + d];
  float acc[9];
#pragma unroll
  for(int k=0;k<8;k++) acc[k] = ln1v * g_I2[k*Dn+d];
  acc[8] = qv * khv;
#pragma unroll
  for(int k=0;k<9;k++) acc[k] = warpSum(acc[k]);
  __shared__ float sm[8*9];
  int w = d>>5, ln = d&31;
  if(ln==0){
#pragma unroll
    for(int k=0;k<9;k++) sm[w*9+k] = acc[k];
  }
  __syncthreads();
  if(d<9){
    float v = 0.f;
    for(int ww=0;ww<8;ww++) v += sm[ww*9+d];
    sm[d] = v;
  }
  __syncthreads();
  if(d==0){
    float m = -1e30f;
    for(int k=0;k<8;k++) m = fmaxf(m, sm[k]*SCALEF);
    float e[8], s = 0.f;
    for(int k=0;k<8;k++){ e[k] = expf(sm[k]*SCALEF - m); s += e[k]; }
    float inv = 1.f/s;
    for(int k=0;k<8;k++) g_score[i*8+k] = e[k]*inv;
    g_qkh[i] = sm[8];
  }
}

// ---------------- 6. GEMM + fused relu + dot-with-q ----------------
// logits_gemm[r] = sum_d q[b(r),d] * relu( sum_j kh[r,j]*W[d,j] + Wb[d] )
#define BKC 16
#define PADA 136   // duplicated-row pitch (floats), keeps 16B alignment
__global__ __launch_bounds__(256,2) void k_gemm(
    const float* __restrict__ xl, const float* __restrict__ xg,
    const float* __restrict__ pos,
    const float* __restrict__ g4, const float* __restrict__ b4,
    const float* __restrict__ Wb){
  int blk = blockIdx.x;
  int which = blk / (BLn/64);
  int tile  = blk - which*(BLn/64);
  const float* x = which ? xg : xl;
  int row0 = tile*64;
  __shared__ __align__(16) float kh[BKC*PADA];   // kh duplicated pairs, transposed
  __shared__ __align__(16) float wts[BKC*Dn];    // Wt rows j0..j0+BKC
  __shared__ float mu2s[64], rs2s[64], red[64];
  int tid = threadIdx.x;
  if(tid < 64){
    float4 st = g_stats[which*BLn + row0 + tid];
    mu2s[tid] = st.z; rs2s[tid] = st.w; red[tid] = 0.f;
  }
  unsigned long long acc[8][4];
#pragma unroll
  for(int i=0;i<8;i++)
#pragma unroll
    for(int c=0;c<4;c++) acc[i][c] = 0ull;
  int rowg = tid>>5, colg = tid&31;
  int r0 = rowg*8, c0 = colg*4;
  int r = tid>>2, q4 = tid&3;
  int grow = row0 + r; int lrow = grow % Ln;
  const float* xrow = &x[grow*Dn];
  const float* prow = &pos[lrow*Dn];
  __syncthreads();

  for(int j0=0;j0<Dn;j0+=BKC){
    { // fill kh tile (64 rows x BKC cols), ln4 applied, duplicated for f32x2
      float mu = mu2s[r], rs = rs2s[r];
      float4 xa = *(const float4*)&xrow[j0 + q4*4];
      float4 pa = *(const float4*)&prow[j0 + q4*4];
      float4 ga = *(const float4*)&g4[j0 + q4*4];
      float4 ba = *(const float4*)&b4[j0 + q4*4];
      float v0 = (xa.x+pa.x-mu)*rs*ga.x + ba.x;
      float v1 = (xa.y+pa.y-mu)*rs*ga.y + ba.y;
      float v2 = (xa.z+pa.z-mu)*rs*ga.z + ba.z;
      float v3 = (xa.w+pa.w-mu)*rs*ga.w + ba.w;
      int jb = q4*4;
      *(float2*)&kh[(jb+0)*PADA + 2*r] = make_float2(v0,v0);
      *(float2*)&kh[(jb+1)*PADA + 2*r] = make_float2(v1,v1);
      *(float2*)&kh[(jb+2)*PADA + 2*r] = make_float2(v2,v2);
      *(float2*)&kh[(jb+3)*PADA + 2*r] = make_float2(v3,v3);
    }
    { // fill wts tile: contiguous 16KB copy
      const float4* src = (const float4*)&g_Wt[j0*Dn];
      float4* dst = (float4*)wts;
#pragma unroll
      for(int u=0;u<4;u++) dst[tid + u*256] = src[tid + u*256];
    }
    __syncthreads();
#pragma unroll 8
    for(int j=0;j<BKC;j++){
      const float* khr = &kh[j*PADA + 2*r0];
      ulonglong2 A0 = *(const ulonglong2*)(khr);
      ulonglong2 A1 = *(const ulonglong2*)(khr+4);
      ulonglong2 A2 = *(const ulonglong2*)(khr+8);
      ulonglong2 A3 = *(const ulonglong2*)(khr+12);
      const float* wr = &wts[j*Dn + c0];
      ulonglong2 Ba = *(const ulonglong2*)(wr);
      ulonglong2 Bb = *(const ulonglong2*)(wr+128);
      unsigned long long a[8] = {A0.x,A0.y,A1.x,A1.y,A2.x,A2.y,A3.x,A3.y};
      unsigned long long bv[4] = {Ba.x,Ba.y,Bb.x,Bb.y};
#pragma unroll
      for(int i=0;i<8;i++){
#pragma unroll
        for(int c=0;c<4;c++) acc[i][c] = fma2u(a[i], bv[c], acc[i][c]);
      }
    }
    __syncthreads();
  }

  // epilogue: relu + bias + dot with q, reduce across columns in smem
  float4 wbA = *(const float4*)&Wb[c0];
  float4 wbB = *(const float4*)&Wb[128 + c0];
#pragma unroll
  for(int i=0;i<8;i++){
    int gr = row0 + r0 + i;
    int bi = gr / Ln;
    const float* qb = &g_q[(which*Bn + bi)*Dn];
    float4 qA = *(const float4*)&qb[c0];
    float4 qB = *(const float4*)&qb[128 + c0];
    float2 v0 = up2(acc[i][0]), v1 = up2(acc[i][1]);
    float2 v2 = up2(acc[i][2]), v3 = up2(acc[i][3]);
    float p = 0.f;
    p += qA.x*fmaxf(v0.x+wbA.x, 0.f);
    p += qA.y*fmaxf(v0.y+wbA.y, 0.f);
    p += qA.z*fmaxf(v1.x+wbA.z, 0.f);
    p += qA.w*fmaxf(v1.y+wbA.w, 0.f);
    p += qB.x*fmaxf(v2.x+wbB.x, 0.f);
    p += qB.y*fmaxf(v2.y+wbB.y, 0.f);
    p += qB.z*fmaxf(v3.x+wbB.z, 0.f);
    p += qB.w*fmaxf(v3.y+wbB.w, 0.f);
    atomicAdd(&red[r0+i], p);
  }
  __syncthreads();
  if(tid < 64) g_glog[which*BLn + row0 + tid] = red[tid];
}

// ---------------- 7. softmax over L ----------------
__global__ void k_wsm(){
  int i = blockIdx.x; int which = i/Bn; int b = i - which*Bn;
  int t = threadIdx.x;
  int rr = which*BLn + b*Ln + t;
  float v = (t < Ln) ? (g_glog[rr] + g_qkh[rr])*SCALEF : -1e30f;
  __shared__ float sm[8]; __shared__ float bc[1];
  int w = t>>5, ln = t&31;
  float m = warpMax(v);
  if(ln==0) sm[w] = m;
  __syncthreads();
  if(t==0){
    float mm = sm[0];
    for(int u=1;u<8;u++) mm = fmaxf(mm, sm[u]);
    bc[0] = mm;
  }
  __syncthreads();
  float mm = bc[0];
  float e = (t < Ln) ? expf(v - mm) : 0.f;
  float s = warpSum(e);
  if(ln==0) sm[w] = s;
  __syncthreads();
  if(t==0){
    float ss = 0.f;
    for(int u=0;u<8;u++) ss += sm[u];
    bc[0] = ss;
  }
  __syncthreads();
  if(t < Ln) g_w[rr] = e / bc[0];
}

// ---------------- 8. output: ln5(fuse*x) summed over branches ----------------
__global__ void k_out(const float* __restrict__ xl, const float* __restrict__ xg,
                      const float* __restrict__ g5, const float* __restrict__ b5,
                      float* __restrict__ out){
  int row = blockIdx.x; int b = row/Ln, l = row - b*Ln; int d = threadIdx.x;
  float4 stL = g_stats[row], stG = g_stats[BLn + row];
  __shared__ float aS[16];
  if(d < 16){
    int which = d>>3, k = d&7;
    int rr = which*BLn + row;
    float f = g_score[rr*8 + k] * g_w[rr];
    float var = which ? stG.y : stL.y;
    aS[d] = f * rsqrtf(f*f*var + EPSF);
  }
  __syncthreads();
  float xlv = xl[row*Dn + d], xgv = xg[row*Dn + d];
  float devL = xlv - stL.x, devG = xgv - stG.x;
  float gg = g5[d], bb = 2.f*b5[d];
  size_t base = (size_t)b*Kn*Ln*Dn + (size_t)l*Dn + d;
#pragma unroll
  for(int k=0;k<8;k++){
    float v = (aS[k]*devL + aS[8+k]*devG)*gg + bb;
    __stcs(&out[base + (size_t)k*Ln*Dn], v);
  }
}

// ---------------- launch ----------------
extern "C" void kernel_launch(void* const* d_in, const int* in_sizes, int n_in,
                              void* d_out, int out_size){
  const float* xl     = (const float*)d_in[0];
  const float* xg     = (const float*)d_in[1];
  const float* intent = (const float*)d_in[2];
  const float* pos    = (const float*)d_in[3];
  const float* rou    = (const float*)d_in[4];
  const float* Ww     = (const float*)d_in[5];
  const float* Wb     = (const float*)d_in[6];
  const float* g1 = (const float*)d_in[7];  const float* b1 = (const float*)d_in[8];
  const float* g2 = (const float*)d_in[9];  const float* b2 = (const float*)d_in[10];
  const float* g3 = (const float*)d_in[11]; const float* b3 = (const float*)d_in[12];
  const float* g4 = (const float*)d_in[13]; const float* b4 = (const float*)d_in[14];
  const float* g5 = (const float*)d_in[15]; const float* b5 = (const float*)d_in[16];
  const int*  seq = (const int*)d_in[17];
  float* out = (float*)d_out;

  k_tr<<<dim3(8,8), dim3(32,32)>>>(Ww);
  k_stats<<<2*BLn, 256>>>(xl, xg, pos);
  k_lnint<<<Kn, 256>>>(intent, g2, b2);
  k_q<<<2*Bn, 256>>>(xl, xg, pos, rou, g3, b3, seq);
  k_score<<<2*BLn, 256>>>(xl, xg, pos, g1, b1, g4, b4);
  k_gemm<<<2*(BLn/64), 256>>>(xl, xg, pos, g4, b4, Wb);
  k_wsm<<<2*Bn, 256>>>();
  k_out<<<BLn, 256>>>(xl, xg, g5, b5, out);
}

// round 3
// speedup vs baseline: 2.3001x; 2.3001x over previous
#include <cuda_runtime.h>
#include <cuda_fp16.h>
#include <cstdint>

#define Bn 64
#define Ln 200
#define Dn 256
#define Kn 8
#define BLn (Bn*Ln)
#define EPSF 1e-5f
#define SCALEF 0.0625f

// ---------------- device scratch ----------------
__device__ float  g_I2[Kn*Dn];        // ln2(intentions)
__device__ float  g_q[2*Bn*Dn];       // ln3(q_row)
__device__ float4 g_stats[2*BLn];     // (mu1, var1, mu2, rstd2)
__device__ float  g_score[2*BLn*Kn];  // softmax over K
__device__ float  g_qkh[2*BLn];       // q . key_hat (raw)
__device__ float  g_glog[2*BLn];      // q . relu(KH W^T + b) (raw)
__device__ float  g_w[2*BLn];         // softmax over L
__device__ __align__(16) __half g_khh[2*BLn*Dn];  // KH hi (fp16)
__device__ __align__(16) __half g_khl[2*BLn*Dn];  // KH lo (fp16)
__device__ __align__(16) __half g_Wh[Dn*Dn];      // W hi
__device__ __align__(16) __half g_Wl[Dn*Dn];      // W lo

// ---------------- helpers ----------------
__device__ __forceinline__ float warpSum(float v){
#pragma unroll
  for(int o=16;o>0;o>>=1) v += __shfl_xor_sync(0xffffffffu, v, o);
  return v;
}
__device__ __forceinline__ void mma16816(float* d, const uint32_t* a, const uint32_t* b){
  asm volatile("mma.sync.aligned.m16n8k16.row.col.f32.f16.f16.f32 "
    "{%0,%1,%2,%3}, {%4,%5,%6,%7}, {%8,%9}, {%0,%1,%2,%3};"
    : "+f"(d[0]), "+f"(d[1]), "+f"(d[2]), "+f"(d[3])
    : "r"(a[0]), "r"(a[1]), "r"(a[2]), "r"(a[3]), "r"(b[0]), "r"(b[1]));
}

// ---------------- 1. fused small kernel: ln2(intentions), q=ln3(...), W split ----------------
__global__ void k_small(const float* __restrict__ xl, const float* __restrict__ xg,
                        const float* __restrict__ intent, const float* __restrict__ pos,
                        const float* __restrict__ rou, const float* __restrict__ Ww,
                        const float* __restrict__ g2, const float* __restrict__ b2,
                        const float* __restrict__ g3, const float* __restrict__ b3,
                        const int* __restrict__ seq){
  int blk = blockIdx.x, d = threadIdx.x;
  if(blk >= Kn + 2*Bn){   // W split blocks
    int i = (blk - (Kn + 2*Bn))*256 + d;
    float w = Ww[i];
    __half h = __float2half_rn(w);
    g_Wh[i] = h;
    g_Wl[i] = __float2half_rn(w - __half2float(h));
    return;
  }
  __shared__ float s1[8], s2[8], res[2];
  float v; float* dst; const float* gg; const float* bb;
  if(blk < Kn){
    v = intent[blk*Dn + d];
    dst = &g_I2[blk*Dn + d]; gg = g2; bb = b2;
  } else {
    int i = blk - Kn; int which = i/Bn; int b = i - which*Bn;
    const float* x = which ? xg : xl;
    int idx = seq[b] - 1;
    v = x[(b*Ln+idx)*Dn + d] + pos[idx*Dn + d] + rou[d];
    dst = &g_q[i*Dn + d]; gg = g3; bb = b3;
  }
  float a = warpSum(v), b2v = warpSum(v*v);
  int w = d>>5, ln = d&31;
  if(ln==0){ s1[w]=a; s2[w]=b2v; }
  __syncthreads();
  if(d==0){
    float t1=0.f, t2=0.f;
    for(int u=0;u<8;u++){ t1+=s1[u]; t2+=s2[u]; }
    float mu=t1/Dn, var=t2/Dn-mu*mu;
    res[0]=mu; res[1]=rsqrtf(var+EPSF);
  }
  __syncthreads();
  dst[0] = (v-res[0])*res[1]*gg[d] + bb[d];
}

// ---------------- 2. warp-per-row: stats + score softmax + q.key_hat + KH fp16 split ----------------
__global__ __launch_bounds__(256) void k_score(
    const float* __restrict__ xl, const float* __restrict__ xg,
    const float* __restrict__ pos,
    const float* __restrict__ g1, const float* __restrict__ b1,
    const float* __restrict__ g4, const float* __restrict__ b4){
  __shared__ float sI2[Kn*Dn];
  __shared__ float sg1[Dn], sb1[Dn], sg4[Dn], sb4[Dn];
  int tid = threadIdx.x;
  {
    const float4* src = (const float4*)g_I2; float4* dst = (float4*)sI2;
    dst[tid] = src[tid]; dst[tid+256] = src[tid+256];
    sg1[tid]=g1[tid]; sb1[tid]=b1[tid]; sg4[tid]=g4[tid]; sb4[tid]=b4[tid];
  }
  __syncthreads();
  int wid = tid>>5, lid = tid&31;
  int i = blockIdx.x*8 + wid;
  int which = i/BLn; int row = i - which*BLn;
  const float* x = which ? xg : xl;
  int b = row/Ln, l = row - b*Ln;
  int d0 = lid*8;
  float xv[8], pv[8];
  *(float4*)&xv[0] = *(const float4*)&x[row*Dn + d0];
  *(float4*)&xv[4] = *(const float4*)&x[row*Dn + d0 + 4];
  *(float4*)&pv[0] = *(const float4*)&pos[l*Dn + d0];
  *(float4*)&pv[4] = *(const float4*)&pos[l*Dn + d0 + 4];
  float s0=0.f,s1=0.f,s2=0.f,s3=0.f;
  float sp[8];
#pragma unroll
  for(int j=0;j<8;j++){
    float a = xv[j]; sp[j] = a + pv[j];
    s0 += a; s1 += a*a; s2 += sp[j]; s3 += sp[j]*sp[j];
  }
  s0 = warpSum(s0); s1 = warpSum(s1); s2 = warpSum(s2); s3 = warpSum(s3);
  float mu1 = s0/Dn, var1 = s1/Dn - mu1*mu1;
  float mu2 = s2/Dn, var2 = s3/Dn - mu2*mu2;
  float rs1 = rsqrtf(var1+EPSF), rs2 = rsqrtf(var2+EPSF);
  float ln1[8], kh[8];
#pragma unroll
  for(int j=0;j<8;j++){
    ln1[j] = (xv[j]-mu1)*rs1*sg1[d0+j] + sb1[d0+j];
    kh[j]  = (sp[j]-mu2)*rs2*sg4[d0+j] + sb4[d0+j];
  }
  { // fp16 hi/lo split of KH -> global
    __half hh[8]; float lo[8];
#pragma unroll
    for(int j=0;j<8;j++){ hh[j] = __float2half_rn(kh[j]); lo[j] = kh[j] - __half2float(hh[j]); }
    uint4 H, L;
    __half2* Hp = (__half2*)&H; __half2* Lp = (__half2*)&L;
#pragma unroll
    for(int j=0;j<4;j++){
      Hp[j] = __halves2half2(hh[2*j], hh[2*j+1]);
      Lp[j] = __floats2half2_rn(lo[2*j], lo[2*j+1]);
    }
    *(uint4*)&g_khh[(size_t)i*Dn + d0] = H;
    *(uint4*)&g_khl[(size_t)i*Dn + d0] = L;
  }
  float qv[8];
  *(float4*)&qv[0] = *(const float4*)&g_q[(which*Bn+b)*Dn + d0];
  *(float4*)&qv[4] = *(const float4*)&g_q[(which*Bn+b)*Dn + d0 + 4];
  float aq = 0.f;
#pragma unroll
  for(int j=0;j<8;j++) aq += qv[j]*kh[j];
  aq = warpSum(aq);
  float sc[8];
#pragma unroll
  for(int k=0;k<8;k++){
    const float* I = &sI2[k*Dn + d0];
    float p = 0.f;
#pragma unroll
    for(int j=0;j<8;j++) p += ln1[j]*I[j];
    sc[k] = warpSum(p);
  }
  if(lid==0){
    g_stats[i] = make_float4(mu1, var1, mu2, rs2);
    g_qkh[i] = aq;
    float m = -1e30f;
#pragma unroll
    for(int k=0;k<8;k++) m = fmaxf(m, sc[k]*SCALEF);
    float e[8], ss = 0.f;
#pragma unroll
    for(int k=0;k<8;k++){ e[k] = expf(sc[k]*SCALEF - m); ss += e[k]; }
    float inv = 1.f/ss;
#pragma unroll
    for(int k=0;k<8;k++) g_score[i*8+k] = e[k]*inv;
  }
}

// ---------------- 3. HMMA GEMM: glog[r] = q . relu(KH W^T + Wb) ----------------
// fp16 split, 3 passes (AhBh + AhBl + AlBh), fp32 accum.
// Block: 64 rows x 256 cols, K chunks of 64. 8 warps = 2m x 4n.
#define PITCH 72              // halves per smem row
#define OFF_AH 0              // 64*72*2  = 9216
#define OFF_AL 9216
#define OFF_BH 18432          // 256*72*2 = 36864
#define OFF_BL 55296
#define OFF_Q0 92160
#define OFF_Q1 93184
#define OFF_WB 94208
#define OFF_RED 95232
#define GEMM_SMEM 95488

__global__ __launch_bounds__(256, 2) void k_gemm(const float* __restrict__ Wb){
  extern __shared__ char smem[];
  __half* sAh = (__half*)(smem + OFF_AH);
  __half* sAl = (__half*)(smem + OFF_AL);
  __half* sBh = (__half*)(smem + OFF_BH);
  __half* sBl = (__half*)(smem + OFF_BL);
  float* s_q0 = (float*)(smem + OFF_Q0);
  float* s_q1 = (float*)(smem + OFF_Q1);
  float* s_wb = (float*)(smem + OFF_WB);
  float* red  = (float*)(smem + OFF_RED);

  int tid = threadIdx.x, lane = tid&31, wid = tid>>5;
  int wm = wid&1, wn = wid>>1;           // 2m x 4n
  int qr = lane>>2, qc = (lane&3)*2;

  int rowG0 = blockIdx.x*64;
  int which = rowG0 / BLn;
  int rowL = rowG0 - which*BLn;
  int b0 = rowL/Ln, b1 = (rowL+63)/Ln;
  int thr = (b0+1)*Ln - rowL;

  s_q0[tid] = g_q[(which*Bn + b0)*Dn + tid];
  s_q1[tid] = g_q[(which*Bn + b1)*Dn + tid];
  s_wb[tid] = Wb[tid];
  if(tid < 64) red[tid] = 0.f;

  float acc[2][8][4];
#pragma unroll
  for(int mt=0;mt<2;mt++)
#pragma unroll
    for(int t=0;t<8;t++)
#pragma unroll
      for(int c=0;c<4;c++) acc[mt][t][c] = 0.f;

  for(int chunk=0; chunk<4; chunk++){
    int j0 = chunk*64;
    __syncthreads();
    // A tiles: 64 rows x 64 halves, hi+lo
#pragma unroll
    for(int it=0; it<2; it++){
      int idx = tid + it*256;
      int r = idx>>3, seg = idx&7;
      *(uint4*)&sAh[r*PITCH + seg*8] = *(const uint4*)&g_khh[(size_t)(rowG0+r)*Dn + j0 + seg*8];
      *(uint4*)&sAl[r*PITCH + seg*8] = *(const uint4*)&g_khl[(size_t)(rowG0+r)*Dn + j0 + seg*8];
    }
    // B tiles: 256 rows x 64 halves, hi+lo
#pragma unroll
    for(int it=0; it<8; it++){
      int idx = tid + it*256;
      int r = idx>>3, seg = idx&7;
      *(uint4*)&sBh[r*PITCH + seg*8] = *(const uint4*)&g_Wh[r*Dn + j0 + seg*8];
      *(uint4*)&sBl[r*PITCH + seg*8] = *(const uint4*)&g_Wl[r*Dn + j0 + seg*8];
    }
    __syncthreads();
#pragma unroll
    for(int ks=0; ks<4; ks++){
      int kk = ks*16 + qc;
      uint32_t ah[2][4], al[2][4];
#pragma unroll
      for(int mt=0; mt<2; mt++){
        const __half* pa = &sAh[(wm*32 + mt*16 + qr)*PITCH + kk];
        const __half* pl = &sAl[(wm*32 + mt*16 + qr)*PITCH + kk];
        ah[mt][0] = *(const uint32_t*)pa;
        ah[mt][1] = *(const uint32_t*)(pa + 8*PITCH);
        ah[mt][2] = *(const uint32_t*)(pa + 8);
        ah[mt][3] = *(const uint32_t*)(pa + 8*PITCH + 8);
        al[mt][0] = *(const uint32_t*)pl;
        al[mt][1] = *(const uint32_t*)(pl + 8*PITCH);
        al[mt][2] = *(const uint32_t*)(pl + 8);
        al[mt][3] = *(const uint32_t*)(pl + 8*PITCH + 8);
      }
#pragma unroll
      for(int t=0; t<8; t++){
        const __half* pb = &sBh[(wn*64 + t*8 + qr)*PITCH + kk];
        const __half* pbl = &sBl[(wn*64 + t*8 + qr)*PITCH + kk];
        uint32_t bh[2], bl[2];
        bh[0] = *(const uint32_t*)pb;
        bh[1] = *(const uint32_t*)(pb + 8);
        bl[0] = *(const uint32_t*)pbl;
        bl[1] = *(const uint32_t*)(pbl + 8);
#pragma unroll
        for(int mt=0; mt<2; mt++){
          mma16816(acc[mt][t], ah[mt], bh);
          mma16816(acc[mt][t], ah[mt], bl);
          mma16816(acc[mt][t], al[mt], bh);
        }
      }
    }
  }
  __syncthreads();
  // epilogue: bias + relu + dot with q, quad-shuffle then smem reduce
#pragma unroll
  for(int mt=0; mt<2; mt++){
    int r0 = wm*32 + mt*16 + qr;
    int r1 = r0 + 8;
    const float* q0p = (r0 < thr) ? s_q0 : s_q1;
    const float* q1p = (r1 < thr) ? s_q0 : s_q1;
    float p0 = 0.f, p1 = 0.f;
#pragma unroll
    for(int t=0; t<8; t++){
      int c0 = wn*64 + t*8 + qc;
      float w0 = s_wb[c0], w1 = s_wb[c0+1];
      p0 += q0p[c0]*fmaxf(acc[mt][t][0]+w0, 0.f) + q0p[c0+1]*fmaxf(acc[mt][t][1]+w1, 0.f);
      p1 += q1p[c0]*fmaxf(acc[mt][t][2]+w0, 0.f) + q1p[c0+1]*fmaxf(acc[mt][t][3]+w1, 0.f);
    }
    p0 += __shfl_xor_sync(0xffffffffu, p0, 1);
    p0 += __shfl_xor_sync(0xffffffffu, p0, 2);
    p1 += __shfl_xor_sync(0xffffffffu, p1, 1);
    p1 += __shfl_xor_sync(0xffffffffu, p1, 2);
    if((lane&3)==0){
      atomicAdd(&red[r0], p0);
      atomicAdd(&red[r1], p1);
    }
  }
  __syncthreads();
  if(tid < 64) g_glog[rowG0 + tid] = red[tid];
}

// ---------------- 4. softmax over L ----------------
__global__ void k_wsm(){
  int i = blockIdx.x; int which = i/Bn; int b = i - which*Bn;
  int t = threadIdx.x;
  int rr = which*BLn + b*Ln + t;
  float v = (t < Ln) ? (g_glog[rr] + g_qkh[rr])*SCALEF : -1e30f;
  __shared__ float sm[8]; __shared__ float bc[1];
  int w = t>>5, ln = t&31;
  float m = v;
#pragma unroll
  for(int o=16;o>0;o>>=1) m = fmaxf(m, __shfl_xor_sync(0xffffffffu, m, o));
  if(ln==0) sm[w] = m;
  __syncthreads();
  if(t==0){
    float mm = sm[0];
    for(int u=1;u<8;u++) mm = fmaxf(mm, sm[u]);
    bc[0] = mm;
  }
  __syncthreads();
  float mm = bc[0];
  float e = (t < Ln) ? expf(v - mm) : 0.f;
  float s = warpSum(e);
  if(ln==0) sm[w] = s;
  __syncthreads();
  if(t==0){
    float ss = 0.f;
    for(int u=0;u<8;u++) ss += sm[u];
    bc[0] = ss;
  }
  __syncthreads();
  if(t < Ln) g_w[rr] = e / bc[0];
}

// ---------------- 5. output: ln5(fuse*x) summed over branches ----------------
__global__ void k_out(const float* __restrict__ xl, const float* __restrict__ xg,
                      const float* __restrict__ g5, const float* __restrict__ b5,
                      float* __restrict__ out){
  int row = blockIdx.x; int b = row/Ln, l = row - b*Ln; int d = threadIdx.x;
  float4 stL = g_stats[row], stG = g_stats[BLn + row];
  __shared__ float aS[16];
  if(d < 16){
    int which = d>>3, k = d&7;
    int rr = which*BLn + row;
    float f = g_score[rr*8 + k] * g_w[rr];
    float var = which ? stG.y : stL.y;
    aS[d] = f * rsqrtf(f*f*var + EPSF);
  }
  __syncthreads();
  float xlv = xl[row*Dn + d], xgv = xg[row*Dn + d];
  float devL = xlv - stL.x, devG = xgv - stG.x;
  float gg = g5[d], bb = 2.f*b5[d];
  size_t base = (size_t)b*Kn*Ln*Dn + (size_t)l*Dn + d;
#pragma unroll
  for(int k=0;k<8;k++){
    float v = (aS[k]*devL + aS[8+k]*devG)*gg + bb;
    __stcs(&out[base + (size_t)k*Ln*Dn], v);
  }
}

// ---------------- launch ----------------
extern "C" void kernel_launch(void* const* d_in, const int* in_sizes, int n_in,
                              void* d_out, int out_size){
  const float* xl     = (const float*)d_in[0];
  const float* xg     = (const float*)d_in[1];
  const float* intent = (const float*)d_in[2];
  const float* pos    = (const float*)d_in[3];
  const float* rou    = (const float*)d_in[4];
  const float* Ww     = (const float*)d_in[5];
  const float* Wb     = (const float*)d_in[6];
  const float* g1 = (const float*)d_in[7];  const float* b1 = (const float*)d_in[8];
  const float* g2 = (const float*)d_in[9];  const float* b2 = (const float*)d_in[10];
  const float* g3 = (const float*)d_in[11]; const float* b3 = (const float*)d_in[12];
  const float* g4 = (const float*)d_in[13]; const float* b4 = (const float*)d_in[14];
  const float* g5 = (const float*)d_in[15]; const float* b5 = (const float*)d_in[16];
  const int*  seq = (const int*)d_in[17];
  float* out = (float*)d_out;

  static int configured = 0;
  if(!configured){
    cudaFuncSetAttribute(k_gemm, cudaFuncAttributeMaxDynamicSharedMemorySize, GEMM_SMEM);
    configured = 1;
  }

  k_small<<<Kn + 2*Bn + Dn, 256>>>(xl, xg, intent, pos, rou, Ww, g2, b2, g3, b3, seq);
  k_score<<<(2*BLn)/8, 256>>>(xl, xg, pos, g1, b1, g4, b4);
  k_gemm<<<(2*BLn)/64, 256, GEMM_SMEM>>>(Wb);
  k_wsm<<<2*Bn, 256>>>();
  k_out<<<BLn, 256>>>(xl, xg, g5, b5, out);
}

// round 4
// speedup vs baseline: 2.5090x; 1.0908x over previous
#include <cuda_runtime.h>
#include <cuda_fp16.h>
#include <cstdint>

#define Bn 64
#define Ln 200
#define Dn 256
#define Kn 8
#define BLn (Bn*Ln)
#define EPSF 1e-5f
#define SCALEF 0.0625f

// ---------------- device scratch ----------------
__device__ float  g_I2[Kn*Dn];        // ln2(intentions)
__device__ float  g_q[2*Bn*Dn];       // ln3(q_row)
__device__ float4 g_stats[2*BLn];     // (mu1, var1, mu2, rstd2)
__device__ float  g_score[2*BLn*Kn];  // softmax over K
__device__ float  g_qkh[2*BLn];       // q . key_hat (raw)
__device__ float  g_glog[2*BLn];      // q . relu(KH W^T + b) (raw)
__device__ float  g_w[2*BLn];         // softmax over L
__device__ __align__(16) __half g_khh[2*BLn*Dn];  // KH (fp16)
__device__ __align__(16) __half g_Wh[Dn*Dn];      // W hi
__device__ __align__(16) __half g_Wl[Dn*Dn];      // W lo

// ---------------- helpers ----------------
__device__ __forceinline__ float warpSum(float v){
#pragma unroll
  for(int o=16;o>0;o>>=1) v += __shfl_xor_sync(0xffffffffu, v, o);
  return v;
}
__device__ __forceinline__ void mma16816(float* d, const uint32_t* a, const uint32_t* b){
  asm volatile("mma.sync.aligned.m16n8k16.row.col.f32.f16.f16.f32 "
    "{%0,%1,%2,%3}, {%4,%5,%6,%7}, {%8,%9}, {%0,%1,%2,%3};"
    : "+f"(d[0]), "+f"(d[1]), "+f"(d[2]), "+f"(d[3])
    : "r"(a[0]), "r"(a[1]), "r"(a[2]), "r"(a[3]), "r"(b[0]), "r"(b[1]));
}
__device__ __forceinline__ void ldsm4(uint32_t* r, const __half* p){
  uint32_t a = (uint32_t)__cvta_generic_to_shared(p);
  asm volatile("ldmatrix.sync.aligned.m8n8.x4.shared.b16 {%0,%1,%2,%3}, [%4];"
    : "=r"(r[0]), "=r"(r[1]), "=r"(r[2]), "=r"(r[3]) : "r"(a));
}

// ---------------- 1. fused small kernel: ln2(intentions), q=ln3(...), W split ----------------
__global__ void k_small(const float* __restrict__ xl, const float* __restrict__ xg,
                        const float* __restrict__ intent, const float* __restrict__ pos,
                        const float* __restrict__ rou, const float* __restrict__ Ww,
                        const float* __restrict__ g2, const float* __restrict__ b2,
                        const float* __restrict__ g3, const float* __restrict__ b3,
                        const int* __restrict__ seq){
  int blk = blockIdx.x, d = threadIdx.x;
  if(blk >= Kn + 2*Bn){   // W split blocks
    int i = (blk - (Kn + 2*Bn))*256 + d;
    float w = Ww[i];
    __half h = __float2half_rn(w);
    g_Wh[i] = h;
    g_Wl[i] = __float2half_rn(w - __half2float(h));
    return;
  }
  __shared__ float s1[8], s2[8], res[2];
  float v; float* dst; const float* gg; const float* bb;
  if(blk < Kn){
    v = intent[blk*Dn + d];
    dst = &g_I2[blk*Dn + d]; gg = g2; bb = b2;
  } else {
    int i = blk - Kn; int which = i/Bn; int b = i - which*Bn;
    const float* x = which ? xg : xl;
    int idx = seq[b] - 1;
    v = x[(b*Ln+idx)*Dn + d] + pos[idx*Dn + d] + rou[d];
    dst = &g_q[i*Dn + d]; gg = g3; bb = b3;
  }
  float a = warpSum(v), b2v = warpSum(v*v);
  int w = d>>5, ln = d&31;
  if(ln==0){ s1[w]=a; s2[w]=b2v; }
  __syncthreads();
  if(d==0){
    float t1=0.f, t2=0.f;
    for(int u=0;u<8;u++){ t1+=s1[u]; t2+=s2[u]; }
    float mu=t1/Dn, var=t2/Dn-mu*mu;
    res[0]=mu; res[1]=rsqrtf(var+EPSF);
  }
  __syncthreads();
  dst[0] = (v-res[0])*res[1]*gg[d] + bb[d];
}

// ---------------- 2. warp-per-row x4: stats + score softmax + q.key_hat + KH fp16 ----------------
__global__ __launch_bounds__(256) void k_score(
    const float* __restrict__ xl, const float* __restrict__ xg,
    const float* __restrict__ pos,
    const float* __restrict__ g1, const float* __restrict__ b1,
    const float* __restrict__ g4, const float* __restrict__ b4){
  __shared__ float sI2[Kn*Dn];
  __shared__ float sg1[Dn], sb1[Dn], sg4[Dn], sb4[Dn];
  int tid = threadIdx.x;
  {
    const float4* src = (const float4*)g_I2; float4* dst = (float4*)sI2;
    dst[tid] = src[tid]; dst[tid+256] = src[tid+256];
    sg1[tid]=g1[tid]; sb1[tid]=b1[tid]; sg4[tid]=g4[tid]; sb4[tid]=b4[tid];
  }
  __syncthreads();
  int wid = tid>>5, lid = tid&31;
  int d0 = lid*8;
  int base = blockIdx.x*32 + wid*4;
#pragma unroll 1
  for(int rr=0; rr<4; rr++){
    int i = base + rr;
    int which = i/BLn; int row = i - which*BLn;
    const float* x = which ? xg : xl;
    int b = row/Ln, l = row - b*Ln;
    float xv[8], pv[8];
    *(float4*)&xv[0] = *(const float4*)&x[row*Dn + d0];
    *(float4*)&xv[4] = *(const float4*)&x[row*Dn + d0 + 4];
    *(float4*)&pv[0] = *(const float4*)&pos[l*Dn + d0];
    *(float4*)&pv[4] = *(const float4*)&pos[l*Dn + d0 + 4];
    float s0=0.f,s1=0.f,s2=0.f,s3=0.f;
    float sp[8];
#pragma unroll
    for(int j=0;j<8;j++){
      float a = xv[j]; sp[j] = a + pv[j];
      s0 += a; s1 += a*a; s2 += sp[j]; s3 += sp[j]*sp[j];
    }
    s0 = warpSum(s0); s1 = warpSum(s1); s2 = warpSum(s2); s3 = warpSum(s3);
    float mu1 = s0/Dn, var1 = s1/Dn - mu1*mu1;
    float mu2 = s2/Dn, var2 = s3/Dn - mu2*mu2;
    float rs1 = rsqrtf(var1+EPSF), rs2 = rsqrtf(var2+EPSF);
    float ln1[8], kh[8];
#pragma unroll
    for(int j=0;j<8;j++){
      ln1[j] = (xv[j]-mu1)*rs1*sg1[d0+j] + sb1[d0+j];
      kh[j]  = (sp[j]-mu2)*rs2*sg4[d0+j] + sb4[d0+j];
    }
    { // fp16 KH -> global
      uint4 H; __half2* Hp = (__half2*)&H;
#pragma unroll
      for(int j=0;j<4;j++) Hp[j] = __floats2half2_rn(kh[2*j], kh[2*j+1]);
      *(uint4*)&g_khh[(size_t)i*Dn + d0] = H;
    }
    float qv[8];
    *(float4*)&qv[0] = *(const float4*)&g_q[(which*Bn+b)*Dn + d0];
    *(float4*)&qv[4] = *(const float4*)&g_q[(which*Bn+b)*Dn + d0 + 4];
    float aq = 0.f;
#pragma unroll
    for(int j=0;j<8;j++) aq += qv[j]*kh[j];
    aq = warpSum(aq);
    float sc[8];
#pragma unroll
    for(int k=0;k<8;k++){
      const float* I = &sI2[k*Dn + d0];
      float p = 0.f;
#pragma unroll
      for(int j=0;j<8;j++) p += ln1[j]*I[j];
      sc[k] = warpSum(p);
    }
    if(lid==0){
      g_stats[i] = make_float4(mu1, var1, mu2, rs2);
      g_qkh[i] = aq;
      float m = -1e30f;
#pragma unroll
      for(int k=0;k<8;k++) m = fmaxf(m, sc[k]*SCALEF);
      float e[8], ss = 0.f;
#pragma unroll
      for(int k=0;k<8;k++){ e[k] = expf(sc[k]*SCALEF - m); ss += e[k]; }
      float inv = 1.f/ss;
#pragma unroll
      for(int k=0;k<8;k++) g_score[i*8+k] = e[k]*inv;
    }
  }
}

// ---------------- 3. HMMA GEMM (2-pass: A fp16, B hi+lo) ----------------
// glog[r] = q . relu(KH W^T + Wb).  Block: 64 rows x 256 cols, K chunks of 64.
#define PITCH 72
#define OFF_A   0          // 64*72*2   = 9216
#define OFF_BH  9216       // 256*72*2  = 36864
#define OFF_BL  46080
#define OFF_Q0  82944
#define OFF_Q1  83968
#define OFF_WB  84992
#define OFF_RED 86016
#define GEMM_SMEM 86272

__global__ __launch_bounds__(256, 2) void k_gemm(const float* __restrict__ Wb){
  extern __shared__ char smem[];
  __half* sA  = (__half*)(smem + OFF_A);
  __half* sBh = (__half*)(smem + OFF_BH);
  __half* sBl = (__half*)(smem + OFF_BL);
  float* s_q0 = (float*)(smem + OFF_Q0);
  float* s_q1 = (float*)(smem + OFF_Q1);
  float* s_wb = (float*)(smem + OFF_WB);
  float* red  = (float*)(smem + OFF_RED);

  int tid = threadIdx.x, lane = tid&31, wid = tid>>5;
  int wm = wid&1, wn = wid>>1;           // 2m x 4n
  int qr = lane>>2, qc = (lane&3)*2;

  int rowG0 = blockIdx.x*64;
  int which = rowG0 / BLn;
  int rowL = rowG0 - which*BLn;
  int b0 = rowL/Ln, b1 = (rowL+63)/Ln;
  int thr = (b0+1)*Ln - rowL;

  s_q0[tid] = g_q[(which*Bn + b0)*Dn + tid];
  s_q1[tid] = g_q[(which*Bn + b1)*Dn + tid];
  s_wb[tid] = Wb[tid];
  if(tid < 64) red[tid] = 0.f;

  // ldmatrix per-lane offsets
  int arow = (lane&7) + ((lane>>3)&1)*8;
  int akoff = ((lane>>4)&1)*8;
  int brow = (lane&7) + ((lane>>4)&1)*8;
  int bkoff = ((lane>>3)&1)*8;

  float acc[2][8][4];
#pragma unroll
  for(int mt=0;mt<2;mt++)
#pragma unroll
    for(int t=0;t<8;t++)
#pragma unroll
      for(int c=0;c<4;c++) acc[mt][t][c] = 0.f;

  for(int chunk=0; chunk<4; chunk++){
    int j0 = chunk*64;
    __syncthreads();
    // A tile: 64 rows x 64 halves
#pragma unroll
    for(int it=0; it<2; it++){
      int idx = tid + it*256;
      int r = idx>>3, seg = idx&7;
      *(uint4*)&sA[r*PITCH + seg*8] = *(const uint4*)&g_khh[(size_t)(rowG0+r)*Dn + j0 + seg*8];
    }
    // B tiles: 256 rows x 64 halves, hi + lo
#pragma unroll
    for(int it=0; it<8; it++){
      int idx = tid + it*256;
      int r = idx>>3, seg = idx&7;
      *(uint4*)&sBh[r*PITCH + seg*8] = *(const uint4*)&g_Wh[r*Dn + j0 + seg*8];
      *(uint4*)&sBl[r*PITCH + seg*8] = *(const uint4*)&g_Wl[r*Dn + j0 + seg*8];
    }
    __syncthreads();
#pragma unroll
    for(int ks=0; ks<4; ks++){
      int kk = ks*16;
      uint32_t a0[4], a1[4];
      ldsm4(a0, &sA[(wm*32 +  0 + arow)*PITCH + kk + akoff]);
      ldsm4(a1, &sA[(wm*32 + 16 + arow)*PITCH + kk + akoff]);
#pragma unroll
      for(int tp=0; tp<4; tp++){
        int t = tp*2;
        uint32_t bh[4], bl[4];
        ldsm4(bh, &sBh[(wn*64 + t*8 + brow)*PITCH + kk + bkoff]);
        ldsm4(bl, &sBl[(wn*64 + t*8 + brow)*PITCH + kk + bkoff]);
        mma16816(acc[0][t],   a0, bh);
        mma16816(acc[0][t],   a0, bl);
        mma16816(acc[1][t],   a1, bh);
        mma16816(acc[1][t],   a1, bl);
        mma16816(acc[0][t+1], a0, bh+2);
        mma16816(acc[0][t+1], a0, bl+2);
        mma16816(acc[1][t+1], a1, bh+2);
        mma16816(acc[1][t+1], a1, bl+2);
      }
    }
  }
  __syncthreads();
  // epilogue: bias + relu + dot with q, quad-shuffle then smem reduce
#pragma unroll
  for(int mt=0; mt<2; mt++){
    int r0 = wm*32 + mt*16 + qr;
    int r1 = r0 + 8;
    const float* q0p = (r0 < thr) ? s_q0 : s_q1;
    const float* q1p = (r1 < thr) ? s_q0 : s_q1;
    float p0 = 0.f, p1 = 0.f;
#pragma unroll
    for(int t=0; t<8; t++){
      int c0 = wn*64 + t*8 + qc;
      float w0 = s_wb[c0], w1 = s_wb[c0+1];
      p0 += q0p[c0]*fmaxf(acc[mt][t][0]+w0, 0.f) + q0p[c0+1]*fmaxf(acc[mt][t][1]+w1, 0.f);
      p1 += q1p[c0]*fmaxf(acc[mt][t][2]+w0, 0.f) + q1p[c0+1]*fmaxf(acc[mt][t][3]+w1, 0.f);
    }
    p0 += __shfl_xor_sync(0xffffffffu, p0, 1);
    p0 += __shfl_xor_sync(0xffffffffu, p0, 2);
    p1 += __shfl_xor_sync(0xffffffffu, p1, 1);
    p1 += __shfl_xor_sync(0xffffffffu, p1, 2);
    if((lane&3)==0){
      atomicAdd(&red[r0], p0);
      atomicAdd(&red[r1], p1);
    }
  }
  __syncthreads();
  if(tid < 64) g_glog[rowG0 + tid] = red[tid];
}

// ---------------- 4. softmax over L ----------------
__global__ void k_wsm(){
  int i = blockIdx.x; int which = i/Bn; int b = i - which*Bn;
  int t = threadIdx.x;
  int rr = which*BLn + b*Ln + t;
  float v = (t < Ln) ? (g_glog[rr] + g_qkh[rr])*SCALEF : -1e30f;
  __shared__ float sm[8]; __shared__ float bc[1];
  int w = t>>5, ln = t&31;
  float m = v;
#pragma unroll
  for(int o=16;o>0;o>>=1) m = fmaxf(m, __shfl_xor_sync(0xffffffffu, m, o));
  if(ln==0) sm[w] = m;
  __syncthreads();
  if(t==0){
    float mm = sm[0];
    for(int u=1;u<8;u++) mm = fmaxf(mm, sm[u]);
    bc[0] = mm;
  }
  __syncthreads();
  float mm = bc[0];
  float e = (t < Ln) ? expf(v - mm) : 0.f;
  float s = warpSum(e);
  if(ln==0) sm[w] = s;
  __syncthreads();
  if(t==0){
    float ss = 0.f;
    for(int u=0;u<8;u++) ss += sm[u];
    bc[0] = ss;
  }
  __syncthreads();
  if(t < Ln) g_w[rr] = e / bc[0];
}

// ---------------- 5. output: ln5(fuse*x) summed over branches, float4 ----------------
__global__ __launch_bounds__(256) void k_out(
    const float* __restrict__ xl, const float* __restrict__ xg,
    const float* __restrict__ g5, const float* __restrict__ b5,
    float* __restrict__ out){
  int tid = threadIdx.x;
  int rloc = tid>>6;
  int row = blockIdx.x*4 + rloc;
  int d = (tid&63)*4;
  __shared__ float aS[4][16];
  if(tid < 64){
    int rl = tid>>4, idx = tid&15;
    int r2 = blockIdx.x*4 + rl;
    int which = idx>>3, k = idx&7;
    int rr = which*BLn + r2;
    float f = g_score[rr*8 + k] * g_w[rr];
    float var = which ? g_stats[BLn + r2].y : g_stats[r2].y;
    aS[rl][idx] = f * rsqrtf(f*f*var + EPSF);
  }
  __syncthreads();
  int b = row/Ln, l = row - b*Ln;
  float muL = g_stats[row].x, muG = g_stats[BLn + row].x;
  float4 xv = *(const float4*)&xl[row*Dn + d];
  float4 gv = *(const float4*)&xg[row*Dn + d];
  float4 g5v = *(const float4*)&g5[d];
  float4 b5v = *(const float4*)&b5[d];
  float dLx = xv.x-muL, dLy = xv.y-muL, dLz = xv.z-muL, dLw = xv.w-muL;
  float dGx = gv.x-muG, dGy = gv.y-muG, dGz = gv.z-muG, dGw = gv.w-muG;
  float bbx = 2.f*b5v.x, bby = 2.f*b5v.y, bbz = 2.f*b5v.z, bbw = 2.f*b5v.w;
  size_t base = (size_t)b*Kn*Ln*Dn + (size_t)l*Dn + d;
#pragma unroll
  for(int k=0;k<8;k++){
    float aL = aS[rloc][k], aG = aS[rloc][8+k];
    float4 v;
    v.x = (aL*dLx + aG*dGx)*g5v.x + bbx;
    v.y = (aL*dLy + aG*dGy)*g5v.y + bby;
    v.z = (aL*dLz + aG*dGz)*g5v.z + bbz;
    v.w = (aL*dLw + aG*dGw)*g5v.w + bbw;
    __stcs((float4*)&out[base + (size_t)k*Ln*Dn], v);
  }
}

// ---------------- launch ----------------
extern "C" void kernel_launch(void* const* d_in, const int* in_sizes, int n_in,
                              void* d_out, int out_size){
  const float* xl     = (const float*)d_in[0];
  const float* xg     = (const float*)d_in[1];
  const float* intent = (const float*)d_in[2];
  const float* pos    = (const float*)d_in[3];
  const float* rou    = (const float*)d_in[4];
  const float* Ww     = (const float*)d_in[5];
  const float* Wb     = (const float*)d_in[6];
  const float* g1 = (const float*)d_in[7];  const float* b1 = (const float*)d_in[8];
  const float* g2 = (const float*)d_in[9];  const float* b2 = (const float*)d_in[10];
  const float* g3 = (const float*)d_in[11]; const float* b3 = (const float*)d_in[12];
  const float* g4 = (const float*)d_in[13]; const float* b4 = (const float*)d_in[14];
  const float* g5 = (const float*)d_in[15]; const float* b5 = (const float*)d_in[16];
  const int*  seq = (const int*)d_in[17];
  float* out = (float*)d_out;

  static int configured = 0;
  if(!configured){
    cudaFuncSetAttribute(k_gemm, cudaFuncAttributeMaxDynamicSharedMemorySize, GEMM_SMEM);
    configured = 1;
  }

  k_small<<<Kn + 2*Bn + Dn, 256>>>(xl, xg, intent, pos, rou, Ww, g2, b2, g3, b3, seq);
  k_score<<<(2*BLn)/32, 256>>>(xl, xg, pos, g1, b1, g4, b4);
  k_gemm<<<(2*BLn)/64, 256, GEMM_SMEM>>>(Wb);
  k_wsm<<<2*Bn, 256>>>();
  k_out<<<BLn/4, 256>>>(xl, xg, g5, b5, out);
}

// round 5
// speedup vs baseline: 2.7990x; 1.1156x over previous
#include <cuda_runtime.h>
#include <cuda_fp16.h>
#include <cstdint>

#define Bn 64
#define Ln 200
#define Dn 256
#define Kn 8
#define BLn (Bn*Ln)
#define EPSF 1e-5f
#define SCALEF 0.0625f

// ---------------- device scratch ----------------
__device__ float  g_I2[Kn*Dn];        // ln2(intentions)
__device__ float  g_q[2*Bn*Dn];       // ln3(q_row)
__device__ float4 g_stats[2*BLn];     // (mu1, var1, mu2, rstd2)
__device__ float  g_score[2*BLn*Kn];  // softmax over K
__device__ float  g_qkh[2*BLn];       // q . key_hat (raw)
__device__ float  g_glogP[2*2*BLn];   // partial q.relu(...) per N-half
__device__ float  g_w[2*BLn];         // softmax over L
__device__ __align__(16) __half g_khh[2*BLn*Dn];  // KH (fp16)
__device__ __align__(16) __half g_Wh[Dn*Dn];      // W (fp16)

// ---------------- helpers ----------------
__device__ __forceinline__ float warpSum(float v){
#pragma unroll
  for(int o=16;o>0;o>>=1) v += __shfl_xor_sync(0xffffffffu, v, o);
  return v;
}
__device__ __forceinline__ void mma16816(float* d, const uint32_t* a, const uint32_t* b){
  asm volatile("mma.sync.aligned.m16n8k16.row.col.f32.f16.f16.f32 "
    "{%0,%1,%2,%3}, {%4,%5,%6,%7}, {%8,%9}, {%0,%1,%2,%3};"
    : "+f"(d[0]), "+f"(d[1]), "+f"(d[2]), "+f"(d[3])
    : "r"(a[0]), "r"(a[1]), "r"(a[2]), "r"(a[3]), "r"(b[0]), "r"(b[1]));
}
__device__ __forceinline__ void ldsm4(uint32_t* r, const __half* p){
  uint32_t a = (uint32_t)__cvta_generic_to_shared(p);
  asm volatile("ldmatrix.sync.aligned.m8n8.x4.shared.b16 {%0,%1,%2,%3}, [%4];"
    : "=r"(r[0]), "=r"(r[1]), "=r"(r[2]), "=r"(r[3]) : "r"(a));
}

// ---------------- 1. fused small kernel: ln2(intentions), q=ln3(...), W fp16 ----------------
__global__ void k_small(const float* __restrict__ xl, const float* __restrict__ xg,
                        const float* __restrict__ intent, const float* __restrict__ pos,
                        const float* __restrict__ rou, const float* __restrict__ Ww,
                        const float* __restrict__ g2, const float* __restrict__ b2,
                        const float* __restrict__ g3, const float* __restrict__ b3,
                        const int* __restrict__ seq){
  int blk = blockIdx.x, d = threadIdx.x;
  if(blk >= Kn + 2*Bn){   // W fp16 blocks (2 values per thread)
    int i = (blk - (Kn + 2*Bn))*512 + d*2;
    float2 w = *(const float2*)&Ww[i];
    *(__half2*)&g_Wh[i] = __floats2half2_rn(w.x, w.y);
    return;
  }
  __shared__ float s1[8], s2[8], res[2];
  float v; float* dst; const float* gg; const float* bb;
  if(blk < Kn){
    v = intent[blk*Dn + d];
    dst = &g_I2[blk*Dn + d]; gg = g2; bb = b2;
  } else {
    int i = blk - Kn; int which = i/Bn; int b = i - which*Bn;
    const float* x = which ? xg : xl;
    int idx = seq[b] - 1;
    v = x[(b*Ln+idx)*Dn + d] + pos[idx*Dn + d] + rou[d];
    dst = &g_q[i*Dn + d]; gg = g3; bb = b3;
  }
  float a = warpSum(v), b2v = warpSum(v*v);
  int w = d>>5, ln = d&31;
  if(ln==0){ s1[w]=a; s2[w]=b2v; }
  __syncthreads();
  if(d==0){
    float t1=0.f, t2=0.f;
    for(int u=0;u<8;u++){ t1+=s1[u]; t2+=s2[u]; }
    float mu=t1/Dn, var=t2/Dn-mu*mu;
    res[0]=mu; res[1]=rsqrtf(var+EPSF);
  }
  __syncthreads();
  dst[0] = (v-res[0])*res[1]*gg[d] + bb[d];
}

// ---------------- 2. warp-per-row x4: stats + score softmax + q.key_hat + KH fp16 ----------------
__global__ __launch_bounds__(256) void k_score(
    const float* __restrict__ xl, const float* __restrict__ xg,
    const float* __restrict__ pos,
    const float* __restrict__ g1, const float* __restrict__ b1,
    const float* __restrict__ g4, const float* __restrict__ b4){
  __shared__ float sI2[Kn*Dn];
  __shared__ float sg1[Dn], sb1[Dn], sg4[Dn], sb4[Dn];
  int tid = threadIdx.x;
  {
    const float4* src = (const float4*)g_I2; float4* dst = (float4*)sI2;
    dst[tid] = src[tid]; dst[tid+256] = src[tid+256];
    sg1[tid]=g1[tid]; sb1[tid]=b1[tid]; sg4[tid]=g4[tid]; sb4[tid]=b4[tid];
  }
  __syncthreads();
  int wid = tid>>5, lid = tid&31;
  int d0 = lid*8;
  int base = blockIdx.x*32 + wid*4;
#pragma unroll 1
  for(int rr=0; rr<4; rr++){
    int i = base + rr;
    int which = i/BLn; int row = i - which*BLn;
    const float* x = which ? xg : xl;
    int b = row/Ln, l = row - b*Ln;
    float xv[8], pv[8];
    *(float4*)&xv[0] = *(const float4*)&x[row*Dn + d0];
    *(float4*)&xv[4] = *(const float4*)&x[row*Dn + d0 + 4];
    *(float4*)&pv[0] = *(const float4*)&pos[l*Dn + d0];
    *(float4*)&pv[4] = *(const float4*)&pos[l*Dn + d0 + 4];
    float s0=0.f,s1=0.f,s2=0.f,s3=0.f;
    float sp[8];
#pragma unroll
    for(int j=0;j<8;j++){
      float a = xv[j]; sp[j] = a + pv[j];
      s0 += a; s1 += a*a; s2 += sp[j]; s3 += sp[j]*sp[j];
    }
    s0 = warpSum(s0); s1 = warpSum(s1); s2 = warpSum(s2); s3 = warpSum(s3);
    float mu1 = s0/Dn, var1 = s1/Dn - mu1*mu1;
    float mu2 = s2/Dn, var2 = s3/Dn - mu2*mu2;
    float rs1 = rsqrtf(var1+EPSF), rs2 = rsqrtf(var2+EPSF);
    float ln1[8], kh[8];
#pragma unroll
    for(int j=0;j<8;j++){
      ln1[j] = (xv[j]-mu1)*rs1*sg1[d0+j] + sb1[d0+j];
      kh[j]  = (sp[j]-mu2)*rs2*sg4[d0+j] + sb4[d0+j];
    }
    { // fp16 KH -> global
      uint4 H; __half2* Hp = (__half2*)&H;
#pragma unroll
      for(int j=0;j<4;j++) Hp[j] = __floats2half2_rn(kh[2*j], kh[2*j+1]);
      *(uint4*)&g_khh[(size_t)i*Dn + d0] = H;
    }
    float qv[8];
    *(float4*)&qv[0] = *(const float4*)&g_q[(which*Bn+b)*Dn + d0];
    *(float4*)&qv[4] = *(const float4*)&g_q[(which*Bn+b)*Dn + d0 + 4];
    float aq = 0.f;
#pragma unroll
    for(int j=0;j<8;j++) aq += qv[j]*kh[j];
    aq = warpSum(aq);
    float sc[8];
#pragma unroll
    for(int k=0;k<8;k++){
      const float* I = &sI2[k*Dn + d0];
      float p = 0.f;
#pragma unroll
      for(int j=0;j<8;j++) p += ln1[j]*I[j];
      sc[k] = warpSum(p);
    }
    if(lid==0){
      g_stats[i] = make_float4(mu1, var1, mu2, rs2);
      g_qkh[i] = aq;
      float m = -1e30f;
#pragma unroll
      for(int k=0;k<8;k++) m = fmaxf(m, sc[k]*SCALEF);
      float e[8], ss = 0.f;
#pragma unroll
      for(int k=0;k<8;k++){ e[k] = expf(sc[k]*SCALEF - m); ss += e[k]; }
      float inv = 1.f/ss;
#pragma unroll
      for(int k=0;k<8;k++) g_score[i*8+k] = e[k]*inv;
    }
  }
}

// ---------------- 3. HMMA GEMM, single fp16 limb, 64x128 tiles, split-N ----------------
#define PITCH 72
#define OFF_A   0          // 64*72*2  = 9216
#define OFF_B   9216       // 128*72*2 = 18432
#define OFF_Q0  27648
#define OFF_Q1  28160
#define OFF_WB  28672
#define OFF_RED 29184
#define GEMM_SMEM 29456

__global__ __launch_bounds__(256, 3) void k_gemm(const float* __restrict__ Wb){
  extern __shared__ char smem[];
  __half* sA  = (__half*)(smem + OFF_A);
  __half* sB  = (__half*)(smem + OFF_B);
  float* s_q0 = (float*)(smem + OFF_Q0);
  float* s_q1 = (float*)(smem + OFF_Q1);
  float* s_wb = (float*)(smem + OFF_WB);
  float* red  = (float*)(smem + OFF_RED);

  int tid = threadIdx.x, lane = tid&31, wid = tid>>5;
  int wm = wid&1, wn = wid>>1;           // 2m x 4n (32x32 per warp)
  int qr = lane>>2, qc = (lane&3)*2;

  int blk = blockIdx.x;
  int nh = blk & 1, rt = blk >> 1;
  int rowG0 = rt*64;
  int which = rowG0 / BLn;
  int rowL = rowG0 - which*BLn;
  int b0 = rowL/Ln, b1 = (rowL+63)/Ln;
  int thr = (b0+1)*Ln - rowL;
  int cb = nh*128;

  if(tid < 128){
    s_q0[tid] = g_q[(which*Bn + b0)*Dn + cb + tid];
    s_q1[tid] = g_q[(which*Bn + b1)*Dn + cb + tid];
    s_wb[tid] = Wb[cb + tid];
  }
  if(tid < 64) red[tid] = 0.f;

  // ldmatrix per-lane offsets
  int arow = (lane&7) + ((lane>>3)&1)*8;
  int akoff = ((lane>>4)&1)*8;
  int brow = (lane&7) + ((lane>>4)&1)*8;
  int bkoff = ((lane>>3)&1)*8;

  float acc[2][4][4];
#pragma unroll
  for(int mt=0;mt<2;mt++)
#pragma unroll
    for(int t=0;t<4;t++)
#pragma unroll
      for(int c=0;c<4;c++) acc[mt][t][c] = 0.f;

  for(int chunk=0; chunk<4; chunk++){
    int j0 = chunk*64;
    __syncthreads();
    // A tile: 64 rows x 64 halves
#pragma unroll
    for(int it=0; it<2; it++){
      int idx = tid + it*256;
      int r = idx>>3, seg = idx&7;
      *(uint4*)&sA[r*PITCH + seg*8] = *(const uint4*)&g_khh[(size_t)(rowG0+r)*Dn + j0 + seg*8];
    }
    // B tile: 128 rows x 64 halves
#pragma unroll
    for(int it=0; it<4; it++){
      int idx = tid + it*256;
      int r = idx>>3, seg = idx&7;
      *(uint4*)&sB[r*PITCH + seg*8] = *(const uint4*)&g_Wh[(cb + r)*Dn + j0 + seg*8];
    }
    __syncthreads();
#pragma unroll
    for(int ks=0; ks<4; ks++){
      int kk = ks*16;
      uint32_t a0[4], a1[4];
      ldsm4(a0, &sA[(wm*32 +  0 + arow)*PITCH + kk + akoff]);
      ldsm4(a1, &sA[(wm*32 + 16 + arow)*PITCH + kk + akoff]);
#pragma unroll
      for(int tp=0; tp<2; tp++){
        int t = tp*2;
        uint32_t bh[4];
        ldsm4(bh, &sB[(wn*32 + t*8 + brow)*PITCH + kk + bkoff]);
        mma16816(acc[0][t],   a0, bh);
        mma16816(acc[1][t],   a1, bh);
        mma16816(acc[0][t+1], a0, bh+2);
        mma16816(acc[1][t+1], a1, bh+2);
      }
    }
  }
  __syncthreads();
  // epilogue: bias + relu + dot with q-slice, quad-shuffle then smem reduce
#pragma unroll
  for(int mt=0; mt<2; mt++){
    int r0 = wm*32 + mt*16 + qr;
    int r1 = r0 + 8;
    const float* q0p = (r0 < thr) ? s_q0 : s_q1;
    const float* q1p = (r1 < thr) ? s_q0 : s_q1;
    float p0 = 0.f, p1 = 0.f;
#pragma unroll
    for(int t=0; t<4; t++){
      int c0 = wn*32 + t*8 + qc;
      float w0 = s_wb[c0], w1 = s_wb[c0+1];
      p0 += q0p[c0]*fmaxf(acc[mt][t][0]+w0, 0.f) + q0p[c0+1]*fmaxf(acc[mt][t][1]+w1, 0.f);
      p1 += q1p[c0]*fmaxf(acc[mt][t][2]+w0, 0.f) + q1p[c0+1]*fmaxf(acc[mt][t][3]+w1, 0.f);
    }
    p0 += __shfl_xor_sync(0xffffffffu, p0, 1);
    p0 += __shfl_xor_sync(0xffffffffu, p0, 2);
    p1 += __shfl_xor_sync(0xffffffffu, p1, 1);
    p1 += __shfl_xor_sync(0xffffffffu, p1, 2);
    if((lane&3)==0){
      atomicAdd(&red[r0], p0);
      atomicAdd(&red[r1], p1);
    }
  }
  __syncthreads();
  if(tid < 64) g_glogP[nh*2*BLn + rowG0 + tid] = red[tid];
}

// ---------------- 4. softmax over L (sums the two N-half partials) ----------------
__global__ void k_wsm(){
  int i = blockIdx.x; int which = i/Bn; int b = i - which*Bn;
  int t = threadIdx.x;
  int rr = which*BLn + b*Ln + t;
  float v = (t < Ln) ? (g_glogP[rr] + g_glogP[2*BLn + rr] + g_qkh[rr])*SCALEF : -1e30f;
  __shared__ float sm[8]; __shared__ float bc[1];
  int w = t>>5, ln = t&31;
  float m = v;
#pragma unroll
  for(int o=16;o>0;o>>=1) m = fmaxf(m, __shfl_xor_sync(0xffffffffu, m, o));
  if(ln==0) sm[w] = m;
  __syncthreads();
  if(t==0){
    float mm = sm[0];
    for(int u=1;u<8;u++) mm = fmaxf(mm, sm[u]);
    bc[0] = mm;
  }
  __syncthreads();
  float mm = bc[0];
  float e = (t < Ln) ? expf(v - mm) : 0.f;
  float s = warpSum(e);
  if(ln==0) sm[w] = s;
  __syncthreads();
  if(t==0){
    float ss = 0.f;
    for(int u=0;u<8;u++) ss += sm[u];
    bc[0] = ss;
  }
  __syncthreads();
  if(t < Ln) g_w[rr] = e / bc[0];
}

// ---------------- 5. output: ln5(fuse*x) summed over branches, float4 ----------------
__global__ __launch_bounds__(256) void k_out(
    const float* __restrict__ xl, const float* __restrict__ xg,
    const float* __restrict__ g5, const float* __restrict__ b5,
    float* __restrict__ out){
  int tid = threadIdx.x;
  int rloc = tid>>6;
  int row = blockIdx.x*4 + rloc;
  int d = (tid&63)*4;
  __shared__ float aS[4][16];
  if(tid < 64){
    int rl = tid>>4, idx = tid&15;
    int r2 = blockIdx.x*4 + rl;
    int which = idx>>3, k = idx&7;
    int rr = which*BLn + r2;
    float f = g_score[rr*8 + k] * g_w[rr];
    float var = which ? g_stats[BLn + r2].y : g_stats[r2].y;
    aS[rl][idx] = f * rsqrtf(f*f*var + EPSF);
  }
  __syncthreads();
  int b = row/Ln, l = row - b*Ln;
  float muL = g_stats[row].x, muG = g_stats[BLn + row].x;
  float4 xv = *(const float4*)&xl[row*Dn + d];
  float4 gv = *(const float4*)&xg[row*Dn + d];
  float4 g5v = *(const float4*)&g5[d];
  float4 b5v = *(const float4*)&b5[d];
  float dLx = xv.x-muL, dLy = xv.y-muL, dLz = xv.z-muL, dLw = xv.w-muL;
  float dGx = gv.x-muG, dGy = gv.y-muG, dGz = gv.z-muG, dGw = gv.w-muG;
  float bbx = 2.f*b5v.x, bby = 2.f*b5v.y, bbz = 2.f*b5v.z, bbw = 2.f*b5v.w;
  size_t base = (size_t)b*Kn*Ln*Dn + (size_t)l*Dn + d;
#pragma unroll
  for(int k=0;k<8;k++){
    float aL = aS[rloc][k], aG = aS[rloc][8+k];
    float4 v;
    v.x = (aL*dLx + aG*dGx)*g5v.x + bbx;
    v.y = (aL*dLy + aG*dGy)*g5v.y + bby;
    v.z = (aL*dLz + aG*dGz)*g5v.z + bbz;
    v.w = (aL*dLw + aG*dGw)*g5v.w + bbw;
    __stcs((float4*)&out[base + (size_t)k*Ln*Dn], v);
  }
}

// ---------------- launch ----------------
extern "C" void kernel_launch(void* const* d_in, const int* in_sizes, int n_in,
                              void* d_out, int out_size){
  const float* xl     = (const float*)d_in[0];
  const float* xg     = (const float*)d_in[1];
  const float* intent = (const float*)d_in[2];
  const float* pos    = (const float*)d_in[3];
  const float* rou    = (const float*)d_in[4];
  const float* Ww     = (const float*)d_in[5];
  const float* Wb     = (const float*)d_in[6];
  const float* g1 = (const float*)d_in[7];  const float* b1 = (const float*)d_in[8];
  const float* g2 = (const float*)d_in[9];  const float* b2 = (const float*)d_in[10];
  const float* g3 = (const float*)d_in[11]; const float* b3 = (const float*)d_in[12];
  const float* g4 = (const float*)d_in[13]; const float* b4 = (const float*)d_in[14];
  const float* g5 = (const float*)d_in[15]; const float* b5 = (const float*)d_in[16];
  const int*  seq = (const int*)d_in[17];
  float* out = (float*)d_out;

  static int configured = 0;
  if(!configured){
    cudaFuncSetAttribute(k_gemm, cudaFuncAttributeMaxDynamicSharedMemorySize, GEMM_SMEM);
    configured = 1;
  }

  k_small<<<Kn + 2*Bn + Dn/2, 256>>>(xl, xg, intent, pos, rou, Ww, g2, b2, g3, b3, seq);
  k_score<<<(2*BLn)/32, 256>>>(xl, xg, pos, g1, b1, g4, b4);
  k_gemm<<<2*(2*BLn)/64, 256, GEMM_SMEM>>>(Wb);
  k_wsm<<<2*Bn, 256>>>();
  k_out<<<BLn/4, 256>>>(xl, xg, g5, b5, out);
}